// round 14
// baseline (speedup 1.0000x reference)
#include <cuda_runtime.h>
#include <cuda_fp16.h>
#include <math.h>
#include <stdint.h>

#define B_DIM 2
#define T_DIM 2048
#define HID 2048
#define NH 16
#define NKV 4
#define HD 128
#define ROWS (B_DIM * T_DIM)          // 4096
#define QW (NH * HD)                  // 2048
#define KW (NKV * HD)                 // 512

// Scratch (device globals: allocation is forbidden)
__device__ __half g_xh[ROWS * HID];   // x in half
__device__ __half g_qh[ROWS * QW];    // Q half (post-rope, pre-scaled)
__device__ __half g_kh[ROWS * KW];    // K half (post-rope)
__device__ __half g_vh[ROWS * KW];    // V half
__device__ __half g_ah[ROWS * QW];    // attn out half
__device__ __half g_wqh[QW * HID];    // Wq^T half [N][K]
__device__ __half g_wkh[KW * HID];
__device__ __half g_wvh[KW * HID];
__device__ __half g_woh[HID * QW];

__device__ __forceinline__ void mma_f16(float* d, const uint32_t* a, const uint32_t* b) {
    asm volatile(
        "mma.sync.aligned.m16n8k16.row.col.f32.f16.f16.f32 "
        "{%0,%1,%2,%3}, {%4,%5,%6,%7}, {%8,%9}, {%0,%1,%2,%3};"
        : "+f"(d[0]), "+f"(d[1]), "+f"(d[2]), "+f"(d[3])
        : "r"(a[0]), "r"(a[1]), "r"(a[2]), "r"(a[3]), "r"(b[0]), "r"(b[1]));
}

__device__ __forceinline__ void ldmx4(
    uint32_t& r0, uint32_t& r1, uint32_t& r2, uint32_t& r3, const void* p)
{
    uint32_t a = (uint32_t)__cvta_generic_to_shared(p);
    asm volatile("ldmatrix.sync.aligned.m8n8.x4.shared.b16 {%0,%1,%2,%3}, [%4];"
                 : "=r"(r0), "=r"(r1), "=r"(r2), "=r"(r3) : "r"(a));
}
__device__ __forceinline__ void ldmx4_trans(
    uint32_t& r0, uint32_t& r1, uint32_t& r2, uint32_t& r3, const void* p)
{
    uint32_t a = (uint32_t)__cvta_generic_to_shared(p);
    asm volatile("ldmatrix.sync.aligned.m8n8.x4.trans.shared.b16 {%0,%1,%2,%3}, [%4];"
                 : "=r"(r0), "=r"(r1), "=r"(r2), "=r"(r3) : "r"(a));
}

__device__ __forceinline__ uint32_t pack2(float a, float b) {
    __half2 h = __floats2half2_rn(a, b);
    return *(uint32_t*)&h;
}

// cp.async.cg: L2-only allocation — staged tiles have no L1 temporal reuse.
__device__ __forceinline__ void cp16(void* dst, const void* src) {
    uint32_t d = (uint32_t)__cvta_generic_to_shared(dst);
    asm volatile("cp.async.cg.shared.global [%0], [%1], 16;" :: "r"(d), "l"(src));
}
__device__ __forceinline__ void cp_commit() { asm volatile("cp.async.commit_group;" ::); }
template<int N> __device__ __forceinline__ void cp_wait() {
    asm volatile("cp.async.wait_group %0;" :: "n"(N));
}

// ---------------------------------------------------------------------------
// Fused pre-pass: cvt x -> half, plus 4 weight transpose+cvt, in one launch.
// ---------------------------------------------------------------------------
#define PP_CVT_BLKS 8192
#define PP_WQ_BLKS 4096
#define PP_WK_BLKS 1024
#define PP_WV_BLKS 1024
#define PP_WO_BLKS 4096
#define PP_TOTAL (PP_CVT_BLKS + PP_WQ_BLKS + PP_WK_BLKS + PP_WV_BLKS + PP_WO_BLKS)

__global__ __launch_bounds__(256) void prepass_kernel(
    const float* __restrict__ x,
    const float* __restrict__ Wq, const float* __restrict__ Wk,
    const float* __restrict__ Wv, const float* __restrict__ Wo,
    __half* __restrict__ xh,
    __half* __restrict__ wqh, __half* __restrict__ wkh,
    __half* __restrict__ wvh, __half* __restrict__ woh)
{
    int bid = blockIdx.x;
    const int tid = threadIdx.x;

    if (bid < PP_CVT_BLKS) {
        int i = bid * 256 + tid;               // float4 index
        float4 v = ((const float4*)x)[i];
        ((__half2*)xh)[2 * i]     = __floats2half2_rn(v.x, v.y);
        ((__half2*)xh)[2 * i + 1] = __floats2half2_rn(v.z, v.w);
        return;
    }
    bid -= PP_CVT_BLKS;

    const float* in; __half* out; int K, N;
    if (bid < PP_WQ_BLKS)                       { in = Wq; out = wqh; K = HID; N = QW; }
    else if (bid < PP_WQ_BLKS + PP_WK_BLKS)     { bid -= PP_WQ_BLKS; in = Wk; out = wkh; K = HID; N = KW; }
    else if (bid < PP_WQ_BLKS + 2 * PP_WK_BLKS) { bid -= PP_WQ_BLKS + PP_WK_BLKS; in = Wv; out = wvh; K = HID; N = KW; }
    else                                        { bid -= PP_WQ_BLKS + 2 * PP_WK_BLKS; in = Wo; out = woh; K = QW; N = HID; }

    __shared__ float tile[32][33];
    const int nbx = N / 32;
    const int n0 = (bid % nbx) * 32;
    const int k0 = (bid / nbx) * 32;
    const int tx = tid & 31, ty = tid >> 5;     // 32 x 8
#pragma unroll
    for (int i = ty; i < 32; i += 8)
        tile[i][tx] = in[(size_t)(k0 + i) * N + n0 + tx];
    __syncthreads();
#pragma unroll
    for (int i = ty; i < 32; i += 8)
        out[(size_t)(n0 + i) * K + k0 + tx] = __float2half_rn(tile[tx][i]);
}

// ---------------------------------------------------------------------------
// fp16 GEMM core: C[128 @bm][128 @bn] = A[*,2048] @ Bt[*,2048]^T
// ldmatrix fragment loads. BK=64, 2-stage cp.async. 8 warps (2x4), 64x32.
// mode 0: fp32 out; 1: half out; 2: half + fused RoPE (qscale folded in).
// ---------------------------------------------------------------------------
#define HST 72
#define HA_STG (128 * HST)            // halves per operand stage
#define NSTG 2
#define GH_SMEM (NSTG * 2 * HA_STG * 2)   // 73728 B
#define SMST 136                      // epilogue scratch stride (halves)

__device__ __forceinline__ void gemm_h_core(
    const __half* __restrict__ A, const __half* __restrict__ Bt,
    float* __restrict__ Cf, __half* __restrict__ Ch,
    int ldc, int bm, int bn, int mode, float qscale,
    const float* __restrict__ cosb, const float* __restrict__ sinb,
    __half* smh)
{
    __half* Ash = smh;
    __half* Bsh = smh + NSTG * HA_STG;
    const int tid = threadIdx.x, lane = tid & 31, warp = tid >> 5;
    const int g = lane >> 2, tq = lane & 3;
    const int wm = (warp >> 2) * 64, wn = (warp & 3) * 32;
    const int lr = lane & 15;               // ldmatrix row within 16
    const int lc = (lane >> 4) * 8;         // ldmatrix k-offset

    float acc[4][4][4];
#pragma unroll
    for (int mi = 0; mi < 4; mi++)
#pragma unroll
        for (int ni = 0; ni < 4; ni++)
#pragma unroll
            for (int r = 0; r < 4; r++) acc[mi][ni][r] = 0.0f;

// BK=64: 128 rows x 8 chunks of 8 halves per operand per stage
#define LOAD_STAGE(st, k0) { \
    __half* Ad = Ash + (st) * HA_STG; \
    __half* Bd = Bsh + (st) * HA_STG; \
    _Pragma("unroll") \
    for (int j = 0; j < 4; j++) { \
        int i = tid + 256 * j; int row = i >> 3; int c = i & 7; \
        cp16(Ad + row * HST + c * 8, A + (size_t)(bm + row) * HID + (k0) + c * 8); \
        cp16(Bd + row * HST + c * 8, Bt + (size_t)(bn + row) * HID + (k0) + c * 8); \
    } \
    cp_commit(); }

    LOAD_STAGE(0, 0)

    const int NT = HID / 64;   // 32
    for (int t = 0; t < NT; t++) {
        cp_wait<0>();
        __syncthreads();
        if (t + 1 < NT) LOAD_STAGE((t + 1) & 1, (t + 1) * 64)

        const __half* Ast = Ash + (t & 1) * HA_STG;
        const __half* Bst = Bsh + (t & 1) * HA_STG;
#pragma unroll
        for (int ks = 0; ks < 4; ks++) {
            const int kh = ks * 16 + lc;
            uint32_t af[4][4], bf[4][2];
#pragma unroll
            for (int mi = 0; mi < 4; mi++)
                ldmx4(af[mi][0], af[mi][1], af[mi][2], af[mi][3],
                      Ast + (wm + mi * 16 + lr) * HST + kh);
#pragma unroll
            for (int nj = 0; nj < 2; nj++) {
                uint32_t r0, r1, r2, r3;
                ldmx4(r0, r1, r2, r3, Bst + (wn + nj * 16 + lr) * HST + kh);
                bf[2 * nj][0] = r0;     bf[2 * nj][1] = r2;
                bf[2 * nj + 1][0] = r1; bf[2 * nj + 1][1] = r3;
            }
#pragma unroll
            for (int mi = 0; mi < 4; mi++)
#pragma unroll
                for (int ni = 0; ni < 4; ni++)
                    mma_f16(acc[mi][ni], af[mi], bf[ni]);
        }
    }
#undef LOAD_STAGE

    if (mode == 2) {
        // stage acc to smem (half), then fused RoPE (+qscale) + half store
        __half* Sm = smh;   // 128 x SMST halves = 34816 B (< GH_SMEM)
        __syncthreads();    // all warps done reading pipeline stages
#pragma unroll
        for (int mi = 0; mi < 4; mi++) {
#pragma unroll
            for (int ni = 0; ni < 4; ni++) {
                const int rl = wm + mi * 16 + g;
                const int cl = wn + ni * 8 + 2 * tq;
                *(__half2*)&Sm[rl * SMST + cl] =
                    __floats2half2_rn(acc[mi][ni][0], acc[mi][ni][1]);
                *(__half2*)&Sm[(rl + 8) * SMST + cl] =
                    __floats2half2_rn(acc[mi][ni][2], acc[mi][ni][3]);
            }
        }
        __syncthreads();

        const int r0 = tid >> 3;          // 0..31
        const int d0 = (tid & 7) * 8;     // 0..56  (d in [0,64))
#pragma unroll
        for (int pass = 0; pass < 4; pass++) {
            const int row = pass * 32 + r0;
            const int grow = bm + row;
            const int tpos = grow & (T_DIM - 1);
            const float* cb = cosb + tpos * HD;
            const float* sb = sinb + tpos * HD;
            __half* dst = Ch + (size_t)grow * ldc + bn;
            const __half* src = Sm + row * SMST;
#pragma unroll
            for (int j = 0; j < 8; j += 2) {
                const int d = d0 + j;
                float x1a = __half2float(src[d]);
                float x1b = __half2float(src[d + 1]);
                float x2a = __half2float(src[d + 64]);
                float x2b = __half2float(src[d + 65]);
                float o1a = (x1a * cb[d]      - x2a * sb[d])      * qscale;
                float o1b = (x1b * cb[d + 1]  - x2b * sb[d + 1])  * qscale;
                float o2a = (x2a * cb[d + 64] + x1a * sb[d + 64]) * qscale;
                float o2b = (x2b * cb[d + 65] + x1b * sb[d + 65]) * qscale;
                *(__half2*)&dst[d]      = __floats2half2_rn(o1a, o1b);
                *(__half2*)&dst[d + 64] = __floats2half2_rn(o2a, o2b);
            }
        }
        return;
    }

#pragma unroll
    for (int mi = 0; mi < 4; mi++) {
#pragma unroll
        for (int ni = 0; ni < 4; ni++) {
            const int row = bm + wm + mi * 16 + g;
            const int col = bn + wn + ni * 8 + 2 * tq;
            if (mode == 1) {
                *(__half2*)&Ch[(size_t)row * ldc + col] =
                    __floats2half2_rn(acc[mi][ni][0], acc[mi][ni][1]);
                *(__half2*)&Ch[(size_t)(row + 8) * ldc + col] =
                    __floats2half2_rn(acc[mi][ni][2], acc[mi][ni][3]);
            } else {
                *(float2*)&Cf[(size_t)row * ldc + col] =
                    make_float2(acc[mi][ni][0], acc[mi][ni][1]);
                *(float2*)&Cf[(size_t)(row + 8) * ldc + col] =
                    make_float2(acc[mi][ni][2], acc[mi][ni][3]);
            }
        }
    }
}

#define ATT_SCALE 0.08838834764831845f   // 1/sqrt(128)

// Fused QKV: bx 0..15 -> Q (half+rope+scale), 16..19 -> K (half+rope), 20..23 -> V
__global__ __launch_bounds__(256, 2) void gemm_qkv_h(
    const __half* __restrict__ x,
    const __half* __restrict__ WqT, const __half* __restrict__ WkT,
    const __half* __restrict__ WvT,
    __half* __restrict__ qp, __half* __restrict__ kp, __half* __restrict__ vp,
    const float* __restrict__ cosb, const float* __restrict__ sinb)
{
    extern __shared__ __half smh[];
    const int bx = blockIdx.x;
    const __half* Bt; __half* Ch; int ldc; int bn; int mode; float qs;
    if (bx < 16)      { Bt = WqT; Ch = qp; ldc = QW; bn = bx * 128; mode = 2; qs = ATT_SCALE; }
    else if (bx < 20) { Bt = WkT; Ch = kp; ldc = KW; bn = (bx - 16) * 128; mode = 2; qs = 1.0f; }
    else              { Bt = WvT; Ch = vp; ldc = KW; bn = (bx - 20) * 128; mode = 1; qs = 1.0f; }
    gemm_h_core(x, Bt, nullptr, Ch, ldc, blockIdx.y * 128, bn, mode, qs, cosb, sinb, smh);
}

__global__ __launch_bounds__(256, 2) void gemm_wo_h(
    const __half* __restrict__ A, const __half* __restrict__ WoT,
    float* __restrict__ C)
{
    extern __shared__ __half smh[];
    gemm_h_core(A, WoT, C, nullptr, HID, blockIdx.y * 128, blockIdx.x * 128, 0, 1.0f,
                nullptr, nullptr, smh);
}

// ---------------------------------------------------------------------------
// fp16 flash attention, FA2-style register P reuse (no P smem, one sync/tile).
// BM=128 (8 warps x m16), BN=128, double-buffered K/V. Q pre-scaled upstream.
// ---------------------------------------------------------------------------
#define FBM 128
#define FBN 128
#define KVST 136                       // halves per K/V row
#define KV_STG (128 * KVST)            // halves per stage
#define FL_SMEM (4 * KV_STG * 2)       // 139264 B

__global__ __launch_bounds__(256, 1) void flash_h16(
    const __half* __restrict__ q, const __half* __restrict__ k,
    const __half* __restrict__ v, __half* __restrict__ o)
{
    extern __shared__ __half smh[];
    __half* Ks = smh;                  // [2][128][136]
    __half* Vs = Ks + 2 * KV_STG;      // [2][128][136]

    const int tid  = threadIdx.x;
    const int lane = tid & 31;
    const int warp = tid >> 5;
    const int g = lane >> 2;
    const int tq = lane & 3;
    const int wm = warp * 16;
    const int lr = lane & 15;
    const int lc = (lane >> 4) * 8;
    const int i0 = (gridDim.x - 1 - (int)blockIdx.x) * FBM;   // heavy CTAs first
    const int h  = blockIdx.y;
    const int b  = blockIdx.z;
    const int kh = h >> 2;

    const __half* qbase = q + ((size_t)b * T_DIM + i0) * QW + h * HD;
    const __half* kbase = k + ((size_t)b * T_DIM) * KW + kh * HD;
    const __half* vbase = v + ((size_t)b * T_DIM) * KW + kh * HD;

    // Q fragments: 8 k16-chunks covering d=128 (already scaled by 1/sqrt(d))
    uint32_t qf[8][4];
    {
        const __half* q0 = qbase + (size_t)(wm + g) * QW;
        const __half* q8 = q0 + (size_t)8 * QW;
#pragma unroll
        for (int kc = 0; kc < 8; kc++) {
            const int c = kc * 16 + 2 * tq;
            qf[kc][0] = *(const uint32_t*)(q0 + c);
            qf[kc][1] = *(const uint32_t*)(q8 + c);
            qf[kc][2] = *(const uint32_t*)(q0 + c + 8);
            qf[kc][3] = *(const uint32_t*)(q8 + c + 8);
        }
    }

    float O[16][4];
#pragma unroll
    for (int ni = 0; ni < 16; ni++)
#pragma unroll
        for (int r = 0; r < 4; r++) O[ni][r] = 0.0f;
    float m0 = -INFINITY, m1 = -INFINITY, l0 = 0.0f, l1 = 0.0f;

    const int row0 = i0 + wm + g;
    const int row1 = row0 + 8;

#define LOAD_KV(st, j0) { \
    __half* Kd = Ks + (st) * KV_STG; \
    __half* Vd = Vs + (st) * KV_STG; \
    _Pragma("unroll") \
    for (int j = 0; j < 8; j++) { \
        int i = tid + 256 * j; int row = i >> 4; int c = i & 15; \
        cp16(Kd + row * KVST + c * 8, kbase + (size_t)((j0) + row) * KW + c * 8); \
        cp16(Vd + row * KVST + c * 8, vbase + (size_t)((j0) + row) * KW + c * 8); \
    } \
    cp_commit(); }

    const int ntiles = i0 / FBN + 1;
    LOAD_KV(0, 0)

    for (int jt = 0; jt < ntiles; jt++) {
        const int j0 = jt * FBN;
        cp_wait<0>();
        __syncthreads();
        if (jt + 1 < ntiles) LOAD_KV((jt + 1) & 1, j0 + FBN)

        const __half* Kst = Ks + (jt & 1) * KV_STG;
        const __half* Vst = Vs + (jt & 1) * KV_STG;

        // S = Q @ K^T : 8 k16-chunks x 16 n8-tiles (K frags via ldmatrix)
        float S[16][4];
#pragma unroll
        for (int ni = 0; ni < 16; ni++)
#pragma unroll
            for (int r = 0; r < 4; r++) S[ni][r] = 0.0f;

#pragma unroll
        for (int kc = 0; kc < 8; kc++) {
#pragma unroll
            for (int nj = 0; nj < 8; nj++) {
                uint32_t r0, r1, r2, r3;
                ldmx4(r0, r1, r2, r3,
                      Kst + (nj * 16 + lr) * KVST + kc * 16 + lc);
                uint32_t b0[2] = {r0, r2}, b1[2] = {r1, r3};
                mma_f16(S[2 * nj],     qf[kc], b0);
                mma_f16(S[2 * nj + 1], qf[kc], b1);
            }
        }

        if (j0 == i0) {   // diagonal tile: causal mask
#pragma unroll
            for (int ni = 0; ni < 16; ni++) {
                const int col = j0 + ni * 8 + 2 * tq;
                if (col     > row0) S[ni][0] = -1e30f;
                if (col + 1 > row0) S[ni][1] = -1e30f;
                if (col     > row1) S[ni][2] = -1e30f;
                if (col + 1 > row1) S[ni][3] = -1e30f;
            }
        }

        // online softmax
        float rm0 = -INFINITY, rm1 = -INFINITY;
#pragma unroll
        for (int ni = 0; ni < 16; ni++) {
            rm0 = fmaxf(rm0, fmaxf(S[ni][0], S[ni][1]));
            rm1 = fmaxf(rm1, fmaxf(S[ni][2], S[ni][3]));
        }
        rm0 = fmaxf(rm0, __shfl_xor_sync(0xffffffffu, rm0, 1));
        rm0 = fmaxf(rm0, __shfl_xor_sync(0xffffffffu, rm0, 2));
        rm1 = fmaxf(rm1, __shfl_xor_sync(0xffffffffu, rm1, 1));
        rm1 = fmaxf(rm1, __shfl_xor_sync(0xffffffffu, rm1, 2));

        const float mn0 = fmaxf(m0, rm0);
        const float mn1 = fmaxf(m1, rm1);
        const float a0 = __expf(m0 - mn0);
        const float a1 = __expf(m1 - mn1);
        m0 = mn0; m1 = mn1;

        float rs0 = 0.0f, rs1 = 0.0f;
#pragma unroll
        for (int ni = 0; ni < 16; ni++) {
            S[ni][0] = __expf(S[ni][0] - mn0);
            S[ni][1] = __expf(S[ni][1] - mn0);
            S[ni][2] = __expf(S[ni][2] - mn1);
            S[ni][3] = __expf(S[ni][3] - mn1);
            rs0 += S[ni][0] + S[ni][1];
            rs1 += S[ni][2] + S[ni][3];
        }
        rs0 += __shfl_xor_sync(0xffffffffu, rs0, 1);
        rs0 += __shfl_xor_sync(0xffffffffu, rs0, 2);
        rs1 += __shfl_xor_sync(0xffffffffu, rs1, 1);
        rs1 += __shfl_xor_sync(0xffffffffu, rs1, 2);
        l0 = l0 * a0 + rs0;
        l1 = l1 * a1 + rs1;

#pragma unroll
        for (int ni = 0; ni < 16; ni++) {
            O[ni][0] *= a0; O[ni][1] *= a0;
            O[ni][2] *= a1; O[ni][3] *= a1;
        }

        // O += P @ V : P comes straight from S registers (FA2 layout identity)
        const int lrow = (lane & 7) + 8 * ((lane >> 3) & 1);
        const int lcol = 8 * (lane >> 4);
#pragma unroll
        for (int kc = 0; kc < 8; kc++) {
            uint32_t pa[4];
            pa[0] = pack2(S[2 * kc][0],     S[2 * kc][1]);
            pa[1] = pack2(S[2 * kc][2],     S[2 * kc][3]);
            pa[2] = pack2(S[2 * kc + 1][0], S[2 * kc + 1][1]);
            pa[3] = pack2(S[2 * kc + 1][2], S[2 * kc + 1][3]);
            const __half* vrow = Vst + (kc * 16 + lrow) * KVST + lcol;
#pragma unroll
            for (int ni2 = 0; ni2 < 8; ni2++) {
                uint32_t r0, r1, r2, r3;
                ldmx4_trans(r0, r1, r2, r3, vrow + ni2 * 16);
                uint32_t b0[2] = {r0, r1}, b1[2] = {r2, r3};
                mma_f16(O[2 * ni2],     pa, b0);
                mma_f16(O[2 * ni2 + 1], pa, b1);
            }
        }
    }
#undef LOAD_KV

    // epilogue: normalize, write half attn
    const float il0 = 1.0f / l0;
    const float il1 = 1.0f / l1;
    __half* ob = o + ((size_t)b * T_DIM + i0) * QW + h * HD;
#pragma unroll
    for (int ni = 0; ni < 16; ni++) {
        *(__half2*)(ob + (size_t)(wm + g) * QW + ni * 8 + 2 * tq) =
            __floats2half2_rn(O[ni][0] * il0, O[ni][1] * il0);
        *(__half2*)(ob + (size_t)(wm + g + 8) * QW + ni * 8 + 2 * tq) =
            __floats2half2_rn(O[ni][2] * il1, O[ni][3] * il1);
    }
}

// ---------------------------------------------------------------------------
extern "C" void kernel_launch(void* const* d_in, const int* in_sizes, int n_in,
                              void* d_out, int out_size)
{
    const float* x    = (const float*)d_in[0];
    const float* cosb = (const float*)d_in[1];
    const float* sinb = (const float*)d_in[2];
    const float* Wq   = (const float*)d_in[3];
    const float* Wk   = (const float*)d_in[4];
    const float* Wv   = (const float*)d_in[5];
    const float* Wo   = (const float*)d_in[6];
    float* out = (float*)d_out;

    __half *xh, *qh, *khh, *vh, *ah, *wqh, *wkh, *wvh, *woh;
    cudaGetSymbolAddress((void**)&xh, g_xh);
    cudaGetSymbolAddress((void**)&qh, g_qh);
    cudaGetSymbolAddress((void**)&khh, g_kh);
    cudaGetSymbolAddress((void**)&vh, g_vh);
    cudaGetSymbolAddress((void**)&ah, g_ah);
    cudaGetSymbolAddress((void**)&wqh, g_wqh);
    cudaGetSymbolAddress((void**)&wkh, g_wkh);
    cudaGetSymbolAddress((void**)&wvh, g_wvh);
    cudaGetSymbolAddress((void**)&woh, g_woh);

    cudaFuncSetAttribute(gemm_qkv_h, cudaFuncAttributeMaxDynamicSharedMemorySize, GH_SMEM);
    cudaFuncSetAttribute(gemm_wo_h, cudaFuncAttributeMaxDynamicSharedMemorySize, GH_SMEM);
    cudaFuncSetAttribute(flash_h16, cudaFuncAttributeMaxDynamicSharedMemorySize, FL_SMEM);

    // Fused pre-pass: x->half and 4 weight transposes in one launch
    prepass_kernel<<<PP_TOTAL, 256>>>(x, Wq, Wk, Wv, Wo, xh, wqh, wkh, wvh, woh);

    // QKV projections with fused RoPE (Q scaled by 1/sqrt(d)) / direct half (V)
    gemm_qkv_h<<<dim3(24, ROWS / 128), 256, GH_SMEM>>>(
        xh, wqh, wkh, wvh, qh, khh, vh, cosb, sinb);

    // Attention (fp16, FA2 register reuse)
    flash_h16<<<dim3(T_DIM / FBM, NH, B_DIM), 256, FL_SMEM>>>(qh, khh, vh, ah);

    // Output projection (fp16)
    gemm_wo_h<<<dim3(HID / 128, ROWS / 128), 256, GH_SMEM>>>(ah, woh, out);
}

// round 15
// speedup vs baseline: 1.0889x; 1.0889x over previous
#include <cuda_runtime.h>
#include <cuda_fp16.h>
#include <math.h>
#include <stdint.h>

#define B_DIM 2
#define T_DIM 2048
#define HID 2048
#define NH 16
#define NKV 4
#define HD 128
#define ROWS (B_DIM * T_DIM)          // 4096
#define QW (NH * HD)                  // 2048
#define KW (NKV * HD)                 // 512

// Scratch (device globals: allocation is forbidden)
__device__ __half g_xh[ROWS * HID];   // x in half
__device__ __half g_qh[ROWS * QW];    // Q half (post-rope, pre-scaled)
__device__ __half g_kh[ROWS * KW];    // K half (post-rope)
__device__ __half g_vh[ROWS * KW];    // V half
__device__ __half g_ah[ROWS * QW];    // attn out half
__device__ __half g_wqh[QW * HID];    // Wq^T half [N][K]
__device__ __half g_wkh[KW * HID];
__device__ __half g_wvh[KW * HID];
__device__ __half g_woh[HID * QW];

__device__ __forceinline__ void mma_f16(float* d, const uint32_t* a, const uint32_t* b) {
    asm volatile(
        "mma.sync.aligned.m16n8k16.row.col.f32.f16.f16.f32 "
        "{%0,%1,%2,%3}, {%4,%5,%6,%7}, {%8,%9}, {%0,%1,%2,%3};"
        : "+f"(d[0]), "+f"(d[1]), "+f"(d[2]), "+f"(d[3])
        : "r"(a[0]), "r"(a[1]), "r"(a[2]), "r"(a[3]), "r"(b[0]), "r"(b[1]));
}

__device__ __forceinline__ void ldmx4(
    uint32_t& r0, uint32_t& r1, uint32_t& r2, uint32_t& r3, const void* p)
{
    uint32_t a = (uint32_t)__cvta_generic_to_shared(p);
    asm volatile("ldmatrix.sync.aligned.m8n8.x4.shared.b16 {%0,%1,%2,%3}, [%4];"
                 : "=r"(r0), "=r"(r1), "=r"(r2), "=r"(r3) : "r"(a));
}
__device__ __forceinline__ void ldmx4_trans(
    uint32_t& r0, uint32_t& r1, uint32_t& r2, uint32_t& r3, const void* p)
{
    uint32_t a = (uint32_t)__cvta_generic_to_shared(p);
    asm volatile("ldmatrix.sync.aligned.m8n8.x4.trans.shared.b16 {%0,%1,%2,%3}, [%4];"
                 : "=r"(r0), "=r"(r1), "=r"(r2), "=r"(r3) : "r"(a));
}

__device__ __forceinline__ uint32_t pack2(float a, float b) {
    __half2 h = __floats2half2_rn(a, b);
    return *(uint32_t*)&h;
}

// cp.async.ca: L1-allocating — cross-CTA panel reuse on the same SM hits L1.
__device__ __forceinline__ void cp16(void* dst, const void* src) {
    uint32_t d = (uint32_t)__cvta_generic_to_shared(dst);
    asm volatile("cp.async.ca.shared.global [%0], [%1], 16;" :: "r"(d), "l"(src));
}
__device__ __forceinline__ void cp_commit() { asm volatile("cp.async.commit_group;" ::); }
template<int N> __device__ __forceinline__ void cp_wait() {
    asm volatile("cp.async.wait_group %0;" :: "n"(N));
}

// ---------------------------------------------------------------------------
// Fused pre-pass: cvt x -> half, plus 4 weight transpose+cvt, in one launch.
// ---------------------------------------------------------------------------
#define PP_CVT_BLKS 8192
#define PP_WQ_BLKS 4096
#define PP_WK_BLKS 1024
#define PP_WV_BLKS 1024
#define PP_WO_BLKS 4096
#define PP_TOTAL (PP_CVT_BLKS + PP_WQ_BLKS + PP_WK_BLKS + PP_WV_BLKS + PP_WO_BLKS)

__global__ __launch_bounds__(256) void prepass_kernel(
    const float* __restrict__ x,
    const float* __restrict__ Wq, const float* __restrict__ Wk,
    const float* __restrict__ Wv, const float* __restrict__ Wo,
    __half* __restrict__ xh,
    __half* __restrict__ wqh, __half* __restrict__ wkh,
    __half* __restrict__ wvh, __half* __restrict__ woh)
{
    int bid = blockIdx.x;
    const int tid = threadIdx.x;

    if (bid < PP_CVT_BLKS) {
        int i = bid * 256 + tid;               // float4 index
        float4 v = ((const float4*)x)[i];
        ((__half2*)xh)[2 * i]     = __floats2half2_rn(v.x, v.y);
        ((__half2*)xh)[2 * i + 1] = __floats2half2_rn(v.z, v.w);
        return;
    }
    bid -= PP_CVT_BLKS;

    const float* in; __half* out; int K, N;
    if (bid < PP_WQ_BLKS)                       { in = Wq; out = wqh; K = HID; N = QW; }
    else if (bid < PP_WQ_BLKS + PP_WK_BLKS)     { bid -= PP_WQ_BLKS; in = Wk; out = wkh; K = HID; N = KW; }
    else if (bid < PP_WQ_BLKS + 2 * PP_WK_BLKS) { bid -= PP_WQ_BLKS + PP_WK_BLKS; in = Wv; out = wvh; K = HID; N = KW; }
    else                                        { bid -= PP_WQ_BLKS + 2 * PP_WK_BLKS; in = Wo; out = woh; K = QW; N = HID; }

    __shared__ float tile[32][33];
    const int nbx = N / 32;
    const int n0 = (bid % nbx) * 32;
    const int k0 = (bid / nbx) * 32;
    const int tx = tid & 31, ty = tid >> 5;     // 32 x 8
#pragma unroll
    for (int i = ty; i < 32; i += 8)
        tile[i][tx] = in[(size_t)(k0 + i) * N + n0 + tx];
    __syncthreads();
#pragma unroll
    for (int i = ty; i < 32; i += 8)
        out[(size_t)(n0 + i) * K + k0 + tx] = __float2half_rn(tile[tx][i]);
}

// ---------------------------------------------------------------------------
// fp16 GEMM core: C[128 @bm][128 @bn] = A[*,2048] @ Bt[*,2048]^T
// ldmatrix fragment loads. BK=64, 2-stage cp.async. 8 warps (2x4), 64x32.
// mode 0: fp32 out; 1: half out; 2: half + fused RoPE (qscale folded in).
// ---------------------------------------------------------------------------
#define HST 72
#define HA_STG (128 * HST)            // halves per operand stage
#define NSTG 2
#define GH_SMEM (NSTG * 2 * HA_STG * 2)   // 73728 B
#define SMST 136                      // epilogue scratch stride (halves)

__device__ __forceinline__ void gemm_h_core(
    const __half* __restrict__ A, const __half* __restrict__ Bt,
    float* __restrict__ Cf, __half* __restrict__ Ch,
    int ldc, int bm, int bn, int mode, float qscale,
    const float* __restrict__ cosb, const float* __restrict__ sinb,
    __half* smh)
{
    __half* Ash = smh;
    __half* Bsh = smh + NSTG * HA_STG;
    const int tid = threadIdx.x, lane = tid & 31, warp = tid >> 5;
    const int g = lane >> 2, tq = lane & 3;
    const int wm = (warp >> 2) * 64, wn = (warp & 3) * 32;
    const int lr = lane & 15;               // ldmatrix row within 16
    const int lc = (lane >> 4) * 8;         // ldmatrix k-offset

    float acc[4][4][4];
#pragma unroll
    for (int mi = 0; mi < 4; mi++)
#pragma unroll
        for (int ni = 0; ni < 4; ni++)
#pragma unroll
            for (int r = 0; r < 4; r++) acc[mi][ni][r] = 0.0f;

// BK=64: 128 rows x 8 chunks of 8 halves per operand per stage
#define LOAD_STAGE(st, k0) { \
    __half* Ad = Ash + (st) * HA_STG; \
    __half* Bd = Bsh + (st) * HA_STG; \
    _Pragma("unroll") \
    for (int j = 0; j < 4; j++) { \
        int i = tid + 256 * j; int row = i >> 3; int c = i & 7; \
        cp16(Ad + row * HST + c * 8, A + (size_t)(bm + row) * HID + (k0) + c * 8); \
        cp16(Bd + row * HST + c * 8, Bt + (size_t)(bn + row) * HID + (k0) + c * 8); \
    } \
    cp_commit(); }

    LOAD_STAGE(0, 0)

    const int NT = HID / 64;   // 32
    for (int t = 0; t < NT; t++) {
        cp_wait<0>();
        __syncthreads();
        if (t + 1 < NT) LOAD_STAGE((t + 1) & 1, (t + 1) * 64)

        const __half* Ast = Ash + (t & 1) * HA_STG;
        const __half* Bst = Bsh + (t & 1) * HA_STG;
#pragma unroll
        for (int ks = 0; ks < 4; ks++) {
            const int kh = ks * 16 + lc;
            uint32_t af[4][4], bf[4][2];
#pragma unroll
            for (int mi = 0; mi < 4; mi++)
                ldmx4(af[mi][0], af[mi][1], af[mi][2], af[mi][3],
                      Ast + (wm + mi * 16 + lr) * HST + kh);
#pragma unroll
            for (int nj = 0; nj < 2; nj++) {
                uint32_t r0, r1, r2, r3;
                ldmx4(r0, r1, r2, r3, Bst + (wn + nj * 16 + lr) * HST + kh);
                bf[2 * nj][0] = r0;     bf[2 * nj][1] = r2;
                bf[2 * nj + 1][0] = r1; bf[2 * nj + 1][1] = r3;
            }
#pragma unroll
            for (int mi = 0; mi < 4; mi++)
#pragma unroll
                for (int ni = 0; ni < 4; ni++)
                    mma_f16(acc[mi][ni], af[mi], bf[ni]);
        }
    }
#undef LOAD_STAGE

    if (mode == 2) {
        // stage acc to smem (half), then fused RoPE (+qscale) + half store
        __half* Sm = smh;   // 128 x SMST halves = 34816 B (< GH_SMEM)
        __syncthreads();    // all warps done reading pipeline stages
#pragma unroll
        for (int mi = 0; mi < 4; mi++) {
#pragma unroll
            for (int ni = 0; ni < 4; ni++) {
                const int rl = wm + mi * 16 + g;
                const int cl = wn + ni * 8 + 2 * tq;
                *(__half2*)&Sm[rl * SMST + cl] =
                    __floats2half2_rn(acc[mi][ni][0], acc[mi][ni][1]);
                *(__half2*)&Sm[(rl + 8) * SMST + cl] =
                    __floats2half2_rn(acc[mi][ni][2], acc[mi][ni][3]);
            }
        }
        __syncthreads();

        const int r0 = tid >> 3;          // 0..31
        const int d0 = (tid & 7) * 8;     // 0..56  (d in [0,64))
#pragma unroll
        for (int pass = 0; pass < 4; pass++) {
            const int row = pass * 32 + r0;
            const int grow = bm + row;
            const int tpos = grow & (T_DIM - 1);
            const float* cb = cosb + tpos * HD;
            const float* sb = sinb + tpos * HD;
            __half* dst = Ch + (size_t)grow * ldc + bn;
            const __half* src = Sm + row * SMST;
#pragma unroll
            for (int j = 0; j < 8; j += 2) {
                const int d = d0 + j;
                float x1a = __half2float(src[d]);
                float x1b = __half2float(src[d + 1]);
                float x2a = __half2float(src[d + 64]);
                float x2b = __half2float(src[d + 65]);
                float o1a = (x1a * cb[d]      - x2a * sb[d])      * qscale;
                float o1b = (x1b * cb[d + 1]  - x2b * sb[d + 1])  * qscale;
                float o2a = (x2a * cb[d + 64] + x1a * sb[d + 64]) * qscale;
                float o2b = (x2b * cb[d + 65] + x1b * sb[d + 65]) * qscale;
                *(__half2*)&dst[d]      = __floats2half2_rn(o1a, o1b);
                *(__half2*)&dst[d + 64] = __floats2half2_rn(o2a, o2b);
            }
        }
        return;
    }

#pragma unroll
    for (int mi = 0; mi < 4; mi++) {
#pragma unroll
        for (int ni = 0; ni < 4; ni++) {
            const int row = bm + wm + mi * 16 + g;
            const int col = bn + wn + ni * 8 + 2 * tq;
            if (mode == 1) {
                *(__half2*)&Ch[(size_t)row * ldc + col] =
                    __floats2half2_rn(acc[mi][ni][0], acc[mi][ni][1]);
                *(__half2*)&Ch[(size_t)(row + 8) * ldc + col] =
                    __floats2half2_rn(acc[mi][ni][2], acc[mi][ni][3]);
            } else {
                *(float2*)&Cf[(size_t)row * ldc + col] =
                    make_float2(acc[mi][ni][0], acc[mi][ni][1]);
                *(float2*)&Cf[(size_t)(row + 8) * ldc + col] =
                    make_float2(acc[mi][ni][2], acc[mi][ni][3]);
            }
        }
    }
}

#define ATT_SCALE 0.08838834764831845f   // 1/sqrt(128)

// Fused QKV: bx 0..15 -> Q (half+rope+scale), 16..19 -> K (half+rope), 20..23 -> V
__global__ __launch_bounds__(256, 2) void gemm_qkv_h(
    const __half* __restrict__ x,
    const __half* __restrict__ WqT, const __half* __restrict__ WkT,
    const __half* __restrict__ WvT,
    __half* __restrict__ qp, __half* __restrict__ kp, __half* __restrict__ vp,
    const float* __restrict__ cosb, const float* __restrict__ sinb)
{
    extern __shared__ __half smh[];
    const int bx = blockIdx.x;
    const __half* Bt; __half* Ch; int ldc; int bn; int mode; float qs;
    if (bx < 16)      { Bt = WqT; Ch = qp; ldc = QW; bn = bx * 128; mode = 2; qs = ATT_SCALE; }
    else if (bx < 20) { Bt = WkT; Ch = kp; ldc = KW; bn = (bx - 16) * 128; mode = 2; qs = 1.0f; }
    else              { Bt = WvT; Ch = vp; ldc = KW; bn = (bx - 20) * 128; mode = 1; qs = 1.0f; }
    gemm_h_core(x, Bt, nullptr, Ch, ldc, blockIdx.y * 128, bn, mode, qs, cosb, sinb, smh);
}

__global__ __launch_bounds__(256, 2) void gemm_wo_h(
    const __half* __restrict__ A, const __half* __restrict__ WoT,
    float* __restrict__ C)
{
    extern __shared__ __half smh[];
    gemm_h_core(A, WoT, C, nullptr, HID, blockIdx.y * 128, blockIdx.x * 128, 0, 1.0f,
                nullptr, nullptr, smh);
}

// ---------------------------------------------------------------------------
// fp16 flash attention, FA2-style register P reuse (no P smem, one sync/tile).
// BM=128 (8 warps x m16), BN=128, double-buffered K/V. Q pre-scaled upstream.
// ---------------------------------------------------------------------------
#define FBM 128
#define FBN 128
#define KVST 136                       // halves per K/V row
#define KV_STG (128 * KVST)            // halves per stage
#define FL_SMEM (4 * KV_STG * 2)       // 139264 B

__global__ __launch_bounds__(256, 1) void flash_h16(
    const __half* __restrict__ q, const __half* __restrict__ k,
    const __half* __restrict__ v, __half* __restrict__ o)
{
    extern __shared__ __half smh[];
    __half* Ks = smh;                  // [2][128][136]
    __half* Vs = Ks + 2 * KV_STG;      // [2][128][136]

    const int tid  = threadIdx.x;
    const int lane = tid & 31;
    const int warp = tid >> 5;
    const int g = lane >> 2;
    const int tq = lane & 3;
    const int wm = warp * 16;
    const int lr = lane & 15;
    const int lc = (lane >> 4) * 8;
    const int i0 = (gridDim.x - 1 - (int)blockIdx.x) * FBM;   // heavy CTAs first
    const int h  = blockIdx.y;
    const int b  = blockIdx.z;
    const int kh = h >> 2;

    const __half* qbase = q + ((size_t)b * T_DIM + i0) * QW + h * HD;
    const __half* kbase = k + ((size_t)b * T_DIM) * KW + kh * HD;
    const __half* vbase = v + ((size_t)b * T_DIM) * KW + kh * HD;

    // Q fragments: 8 k16-chunks covering d=128 (already scaled by 1/sqrt(d))
    uint32_t qf[8][4];
    {
        const __half* q0 = qbase + (size_t)(wm + g) * QW;
        const __half* q8 = q0 + (size_t)8 * QW;
#pragma unroll
        for (int kc = 0; kc < 8; kc++) {
            const int c = kc * 16 + 2 * tq;
            qf[kc][0] = *(const uint32_t*)(q0 + c);
            qf[kc][1] = *(const uint32_t*)(q8 + c);
            qf[kc][2] = *(const uint32_t*)(q0 + c + 8);
            qf[kc][3] = *(const uint32_t*)(q8 + c + 8);
        }
    }

    float O[16][4];
#pragma unroll
    for (int ni = 0; ni < 16; ni++)
#pragma unroll
        for (int r = 0; r < 4; r++) O[ni][r] = 0.0f;
    float m0 = -INFINITY, m1 = -INFINITY, l0 = 0.0f, l1 = 0.0f;

    const int row0 = i0 + wm + g;
    const int row1 = row0 + 8;

#define LOAD_KV(st, j0) { \
    __half* Kd = Ks + (st) * KV_STG; \
    __half* Vd = Vs + (st) * KV_STG; \
    _Pragma("unroll") \
    for (int j = 0; j < 8; j++) { \
        int i = tid + 256 * j; int row = i >> 4; int c = i & 15; \
        cp16(Kd + row * KVST + c * 8, kbase + (size_t)((j0) + row) * KW + c * 8); \
        cp16(Vd + row * KVST + c * 8, vbase + (size_t)((j0) + row) * KW + c * 8); \
    } \
    cp_commit(); }

    const int ntiles = i0 / FBN + 1;
    LOAD_KV(0, 0)

    for (int jt = 0; jt < ntiles; jt++) {
        const int j0 = jt * FBN;
        cp_wait<0>();
        __syncthreads();
        if (jt + 1 < ntiles) LOAD_KV((jt + 1) & 1, j0 + FBN)

        const __half* Kst = Ks + (jt & 1) * KV_STG;
        const __half* Vst = Vs + (jt & 1) * KV_STG;

        // S = Q @ K^T : 8 k16-chunks x 16 n8-tiles (K frags via ldmatrix)
        float S[16][4];
#pragma unroll
        for (int ni = 0; ni < 16; ni++)
#pragma unroll
            for (int r = 0; r < 4; r++) S[ni][r] = 0.0f;

#pragma unroll
        for (int kc = 0; kc < 8; kc++) {
#pragma unroll
            for (int nj = 0; nj < 8; nj++) {
                uint32_t r0, r1, r2, r3;
                ldmx4(r0, r1, r2, r3,
                      Kst + (nj * 16 + lr) * KVST + kc * 16 + lc);
                uint32_t b0[2] = {r0, r2}, b1[2] = {r1, r3};
                mma_f16(S[2 * nj],     qf[kc], b0);
                mma_f16(S[2 * nj + 1], qf[kc], b1);
            }
        }

        if (j0 == i0) {   // diagonal tile: causal mask
#pragma unroll
            for (int ni = 0; ni < 16; ni++) {
                const int col = j0 + ni * 8 + 2 * tq;
                if (col     > row0) S[ni][0] = -1e30f;
                if (col + 1 > row0) S[ni][1] = -1e30f;
                if (col     > row1) S[ni][2] = -1e30f;
                if (col + 1 > row1) S[ni][3] = -1e30f;
            }
        }

        // online softmax
        float rm0 = -INFINITY, rm1 = -INFINITY;
#pragma unroll
        for (int ni = 0; ni < 16; ni++) {
            rm0 = fmaxf(rm0, fmaxf(S[ni][0], S[ni][1]));
            rm1 = fmaxf(rm1, fmaxf(S[ni][2], S[ni][3]));
        }
        rm0 = fmaxf(rm0, __shfl_xor_sync(0xffffffffu, rm0, 1));
        rm0 = fmaxf(rm0, __shfl_xor_sync(0xffffffffu, rm0, 2));
        rm1 = fmaxf(rm1, __shfl_xor_sync(0xffffffffu, rm1, 1));
        rm1 = fmaxf(rm1, __shfl_xor_sync(0xffffffffu, rm1, 2));

        const float mn0 = fmaxf(m0, rm0);
        const float mn1 = fmaxf(m1, rm1);
        const float a0 = __expf(m0 - mn0);
        const float a1 = __expf(m1 - mn1);
        m0 = mn0; m1 = mn1;

        float rs0 = 0.0f, rs1 = 0.0f;
#pragma unroll
        for (int ni = 0; ni < 16; ni++) {
            S[ni][0] = __expf(S[ni][0] - mn0);
            S[ni][1] = __expf(S[ni][1] - mn0);
            S[ni][2] = __expf(S[ni][2] - mn1);
            S[ni][3] = __expf(S[ni][3] - mn1);
            rs0 += S[ni][0] + S[ni][1];
            rs1 += S[ni][2] + S[ni][3];
        }
        rs0 += __shfl_xor_sync(0xffffffffu, rs0, 1);
        rs0 += __shfl_xor_sync(0xffffffffu, rs0, 2);
        rs1 += __shfl_xor_sync(0xffffffffu, rs1, 1);
        rs1 += __shfl_xor_sync(0xffffffffu, rs1, 2);
        l0 = l0 * a0 + rs0;
        l1 = l1 * a1 + rs1;

#pragma unroll
        for (int ni = 0; ni < 16; ni++) {
            O[ni][0] *= a0; O[ni][1] *= a0;
            O[ni][2] *= a1; O[ni][3] *= a1;
        }

        // O += P @ V : P comes straight from S registers (FA2 layout identity)
        const int lrow = (lane & 7) + 8 * ((lane >> 3) & 1);
        const int lcol = 8 * (lane >> 4);
#pragma unroll
        for (int kc = 0; kc < 8; kc++) {
            uint32_t pa[4];
            pa[0] = pack2(S[2 * kc][0],     S[2 * kc][1]);
            pa[1] = pack2(S[2 * kc][2],     S[2 * kc][3]);
            pa[2] = pack2(S[2 * kc + 1][0], S[2 * kc + 1][1]);
            pa[3] = pack2(S[2 * kc + 1][2], S[2 * kc + 1][3]);
            const __half* vrow = Vst + (kc * 16 + lrow) * KVST + lcol;
#pragma unroll
            for (int ni2 = 0; ni2 < 8; ni2++) {
                uint32_t r0, r1, r2, r3;
                ldmx4_trans(r0, r1, r2, r3, vrow + ni2 * 16);
                uint32_t b0[2] = {r0, r1}, b1[2] = {r2, r3};
                mma_f16(O[2 * ni2],     pa, b0);
                mma_f16(O[2 * ni2 + 1], pa, b1);
            }
        }
    }
#undef LOAD_KV

    // epilogue: normalize, write half attn
    const float il0 = 1.0f / l0;
    const float il1 = 1.0f / l1;
    __half* ob = o + ((size_t)b * T_DIM + i0) * QW + h * HD;
#pragma unroll
    for (int ni = 0; ni < 16; ni++) {
        *(__half2*)(ob + (size_t)(wm + g) * QW + ni * 8 + 2 * tq) =
            __floats2half2_rn(O[ni][0] * il0, O[ni][1] * il0);
        *(__half2*)(ob + (size_t)(wm + g + 8) * QW + ni * 8 + 2 * tq) =
            __floats2half2_rn(O[ni][2] * il1, O[ni][3] * il1);
    }
}

// ---------------------------------------------------------------------------
extern "C" void kernel_launch(void* const* d_in, const int* in_sizes, int n_in,
                              void* d_out, int out_size)
{
    const float* x    = (const float*)d_in[0];
    const float* cosb = (const float*)d_in[1];
    const float* sinb = (const float*)d_in[2];
    const float* Wq   = (const float*)d_in[3];
    const float* Wk   = (const float*)d_in[4];
    const float* Wv   = (const float*)d_in[5];
    const float* Wo   = (const float*)d_in[6];
    float* out = (float*)d_out;

    __half *xh, *qh, *khh, *vh, *ah, *wqh, *wkh, *wvh, *woh;
    cudaGetSymbolAddress((void**)&xh, g_xh);
    cudaGetSymbolAddress((void**)&qh, g_qh);
    cudaGetSymbolAddress((void**)&khh, g_kh);
    cudaGetSymbolAddress((void**)&vh, g_vh);
    cudaGetSymbolAddress((void**)&ah, g_ah);
    cudaGetSymbolAddress((void**)&wqh, g_wqh);
    cudaGetSymbolAddress((void**)&wkh, g_wkh);
    cudaGetSymbolAddress((void**)&wvh, g_wvh);
    cudaGetSymbolAddress((void**)&woh, g_woh);

    cudaFuncSetAttribute(gemm_qkv_h, cudaFuncAttributeMaxDynamicSharedMemorySize, GH_SMEM);
    cudaFuncSetAttribute(gemm_wo_h, cudaFuncAttributeMaxDynamicSharedMemorySize, GH_SMEM);
    cudaFuncSetAttribute(flash_h16, cudaFuncAttributeMaxDynamicSharedMemorySize, FL_SMEM);

    // Fused pre-pass: x->half and 4 weight transposes in one launch
    prepass_kernel<<<PP_TOTAL, 256>>>(x, Wq, Wk, Wv, Wo, xh, wqh, wkh, wvh, woh);

    // QKV projections with fused RoPE (Q scaled by 1/sqrt(d)) / direct half (V)
    gemm_qkv_h<<<dim3(24, ROWS / 128), 256, GH_SMEM>>>(
        xh, wqh, wkh, wvh, qh, khh, vh, cosb, sinb);

    // Attention (fp16, FA2 register reuse)
    flash_h16<<<dim3(T_DIM / FBM, NH, B_DIM), 256, FL_SMEM>>>(qh, khh, vh, ah);

    // Output projection (fp16)
    gemm_wo_h<<<dim3(HID / 128, ROWS / 128), 256, GH_SMEM>>>(ah, woh, out);
}

// round 16
// speedup vs baseline: 1.1011x; 1.0111x over previous
#include <cuda_runtime.h>
#include <cuda_fp16.h>
#include <math.h>
#include <stdint.h>

#define B_DIM 2
#define T_DIM 2048
#define HID 2048
#define NH 16
#define NKV 4
#define HD 128
#define ROWS (B_DIM * T_DIM)          // 4096
#define QW (NH * HD)                  // 2048
#define KW (NKV * HD)                 // 512

// Scratch (device globals: allocation is forbidden)
__device__ __half g_xh[ROWS * HID];   // x in half
__device__ __half g_qh[ROWS * QW];    // Q half (post-rope, pre-scaled)
__device__ __half g_kh[ROWS * KW];    // K half (post-rope)
__device__ __half g_vh[ROWS * KW];    // V half
__device__ __half g_ah[ROWS * QW];    // attn out half
__device__ __half g_wqh[QW * HID];    // Wq^T half [N][K]
__device__ __half g_wkh[KW * HID];
__device__ __half g_wvh[KW * HID];
__device__ __half g_woh[HID * QW];

__device__ __forceinline__ void mma_f16(float* d, const uint32_t* a, const uint32_t* b) {
    asm volatile(
        "mma.sync.aligned.m16n8k16.row.col.f32.f16.f16.f32 "
        "{%0,%1,%2,%3}, {%4,%5,%6,%7}, {%8,%9}, {%0,%1,%2,%3};"
        : "+f"(d[0]), "+f"(d[1]), "+f"(d[2]), "+f"(d[3])
        : "r"(a[0]), "r"(a[1]), "r"(a[2]), "r"(a[3]), "r"(b[0]), "r"(b[1]));
}

__device__ __forceinline__ void ldmx4(
    uint32_t& r0, uint32_t& r1, uint32_t& r2, uint32_t& r3, const void* p)
{
    uint32_t a = (uint32_t)__cvta_generic_to_shared(p);
    asm volatile("ldmatrix.sync.aligned.m8n8.x4.shared.b16 {%0,%1,%2,%3}, [%4];"
                 : "=r"(r0), "=r"(r1), "=r"(r2), "=r"(r3) : "r"(a));
}
__device__ __forceinline__ void ldmx4_trans(
    uint32_t& r0, uint32_t& r1, uint32_t& r2, uint32_t& r3, const void* p)
{
    uint32_t a = (uint32_t)__cvta_generic_to_shared(p);
    asm volatile("ldmatrix.sync.aligned.m8n8.x4.trans.shared.b16 {%0,%1,%2,%3}, [%4];"
                 : "=r"(r0), "=r"(r1), "=r"(r2), "=r"(r3) : "r"(a));
}

__device__ __forceinline__ uint32_t pack2(float a, float b) {
    __half2 h = __floats2half2_rn(a, b);
    return *(uint32_t*)&h;
}

// cp.async.ca: L1-allocating — cross-CTA panel reuse on the same SM hits L1.
__device__ __forceinline__ void cp16(void* dst, const void* src) {
    uint32_t d = (uint32_t)__cvta_generic_to_shared(dst);
    asm volatile("cp.async.ca.shared.global [%0], [%1], 16;" :: "r"(d), "l"(src));
}
__device__ __forceinline__ void cp_commit() { asm volatile("cp.async.commit_group;" ::); }
template<int N> __device__ __forceinline__ void cp_wait() {
    asm volatile("cp.async.wait_group %0;" :: "n"(N));
}

// ---------------------------------------------------------------------------
// Fused pre-pass: cvt x -> half, plus 4 weight transpose+cvt, in one launch.
// ---------------------------------------------------------------------------
#define PP_CVT_BLKS 8192
#define PP_WQ_BLKS 4096
#define PP_WK_BLKS 1024
#define PP_WV_BLKS 1024
#define PP_WO_BLKS 4096
#define PP_TOTAL (PP_CVT_BLKS + PP_WQ_BLKS + PP_WK_BLKS + PP_WV_BLKS + PP_WO_BLKS)

__global__ __launch_bounds__(256) void prepass_kernel(
    const float* __restrict__ x,
    const float* __restrict__ Wq, const float* __restrict__ Wk,
    const float* __restrict__ Wv, const float* __restrict__ Wo,
    __half* __restrict__ xh,
    __half* __restrict__ wqh, __half* __restrict__ wkh,
    __half* __restrict__ wvh, __half* __restrict__ woh)
{
    int bid = blockIdx.x;
    const int tid = threadIdx.x;

    if (bid < PP_CVT_BLKS) {
        int i = bid * 256 + tid;               // float4 index
        float4 v = ((const float4*)x)[i];
        ((__half2*)xh)[2 * i]     = __floats2half2_rn(v.x, v.y);
        ((__half2*)xh)[2 * i + 1] = __floats2half2_rn(v.z, v.w);
        return;
    }
    bid -= PP_CVT_BLKS;

    const float* in; __half* out; int K, N;
    if (bid < PP_WQ_BLKS)                       { in = Wq; out = wqh; K = HID; N = QW; }
    else if (bid < PP_WQ_BLKS + PP_WK_BLKS)     { bid -= PP_WQ_BLKS; in = Wk; out = wkh; K = HID; N = KW; }
    else if (bid < PP_WQ_BLKS + 2 * PP_WK_BLKS) { bid -= PP_WQ_BLKS + PP_WK_BLKS; in = Wv; out = wvh; K = HID; N = KW; }
    else                                        { bid -= PP_WQ_BLKS + 2 * PP_WK_BLKS; in = Wo; out = woh; K = QW; N = HID; }

    __shared__ float tile[32][33];
    const int nbx = N / 32;
    const int n0 = (bid % nbx) * 32;
    const int k0 = (bid / nbx) * 32;
    const int tx = tid & 31, ty = tid >> 5;     // 32 x 8
#pragma unroll
    for (int i = ty; i < 32; i += 8)
        tile[i][tx] = in[(size_t)(k0 + i) * N + n0 + tx];
    __syncthreads();
#pragma unroll
    for (int i = ty; i < 32; i += 8)
        out[(size_t)(n0 + i) * K + k0 + tx] = __float2half_rn(tile[tx][i]);
}

// ---------------------------------------------------------------------------
// fp16 GEMM core: C[128 @bm][128 @bn] = A[*,2048] @ Bt[*,2048]^T
// ldmatrix fragment loads. BK=64, 2-stage cp.async. 8 warps (2x4), 64x32.
// mode 0: fp32 out; 1: half out; 2: half + in-register RoPE via permuted-B
// load (smem row 2j <- n j, row 2j+1 <- n j+64, so each thread's fragment
// pair (c0,c1) is exactly the rope pair (d, d+64)). cos[d+64]==cos[d].
// ---------------------------------------------------------------------------
#define HST 72
#define HA_STG (128 * HST)            // halves per operand stage
#define NSTG 2
#define GH_SMEM (NSTG * 2 * HA_STG * 2)   // 73728 B

__device__ __forceinline__ void gemm_h_core(
    const __half* __restrict__ A, const __half* __restrict__ Bt,
    float* __restrict__ Cf, __half* __restrict__ Ch,
    int ldc, int bm, int bn, int mode, float qscale,
    const float* __restrict__ cosb, const float* __restrict__ sinb,
    __half* smh)
{
    __half* Ash = smh;
    __half* Bsh = smh + NSTG * HA_STG;
    const int tid = threadIdx.x, lane = tid & 31, warp = tid >> 5;
    const int g = lane >> 2, tq = lane & 3;
    const int wm = (warp >> 2) * 64, wn = (warp & 3) * 32;
    const int lr = lane & 15;               // ldmatrix row within 16
    const int lc = (lane >> 4) * 8;         // ldmatrix k-offset
    const bool perm = (mode == 2);          // rope column pairing

    float acc[4][4][4];
#pragma unroll
    for (int mi = 0; mi < 4; mi++)
#pragma unroll
        for (int ni = 0; ni < 4; ni++)
#pragma unroll
            for (int r = 0; r < 4; r++) acc[mi][ni][r] = 0.0f;

// BK=64: 128 rows x 8 chunks of 8 halves per operand per stage.
// B row permuted for mode 2: smem row r <- n = (r&1) ? 64+(r>>1) : (r>>1).
#define LOAD_STAGE(st, k0) { \
    __half* Ad = Ash + (st) * HA_STG; \
    __half* Bd = Bsh + (st) * HA_STG; \
    _Pragma("unroll") \
    for (int j = 0; j < 4; j++) { \
        int i = tid + 256 * j; int row = i >> 3; int c = i & 7; \
        int brow = perm ? (((row & 1) ? 64 : 0) + (row >> 1)) : row; \
        cp16(Ad + row * HST + c * 8, A + (size_t)(bm + row) * HID + (k0) + c * 8); \
        cp16(Bd + row * HST + c * 8, Bt + (size_t)(bn + brow) * HID + (k0) + c * 8); \
    } \
    cp_commit(); }

    LOAD_STAGE(0, 0)

    const int NT = HID / 64;   // 32
    for (int t = 0; t < NT; t++) {
        cp_wait<0>();
        __syncthreads();
        if (t + 1 < NT) LOAD_STAGE((t + 1) & 1, (t + 1) * 64)

        const __half* Ast = Ash + (t & 1) * HA_STG;
        const __half* Bst = Bsh + (t & 1) * HA_STG;
#pragma unroll
        for (int ks = 0; ks < 4; ks++) {
            const int kh = ks * 16 + lc;
            uint32_t af[4][4], bf[4][2];
#pragma unroll
            for (int mi = 0; mi < 4; mi++)
                ldmx4(af[mi][0], af[mi][1], af[mi][2], af[mi][3],
                      Ast + (wm + mi * 16 + lr) * HST + kh);
#pragma unroll
            for (int nj = 0; nj < 2; nj++) {
                uint32_t r0, r1, r2, r3;
                ldmx4(r0, r1, r2, r3, Bst + (wn + nj * 16 + lr) * HST + kh);
                bf[2 * nj][0] = r0;     bf[2 * nj][1] = r2;
                bf[2 * nj + 1][0] = r1; bf[2 * nj + 1][1] = r3;
            }
#pragma unroll
            for (int mi = 0; mi < 4; mi++)
#pragma unroll
                for (int ni = 0; ni < 4; ni++)
                    mma_f16(acc[mi][ni], af[mi], bf[ni]);
        }
    }
#undef LOAD_STAGE

    if (mode == 2) {
        // In-register RoPE: fragment pair (c0,c1)/(c2,c3) = values at (d, d+64).
        // d = wn/2 + ni*4 + tq. cos/sin tables have duplicated halves
        // (emb = concat(freqs, freqs)), so cos[d+64]==cos[d], sin likewise.
        const int dbase = (wn >> 1);
#pragma unroll
        for (int mi = 0; mi < 4; mi++) {
            const int r0g = bm + wm + mi * 16 + g;
            const int r1g = r0g + 8;
            const float* cb0 = cosb + (size_t)(r0g & (T_DIM - 1)) * HD;
            const float* sb0 = sinb + (size_t)(r0g & (T_DIM - 1)) * HD;
            const float* cb1 = cosb + (size_t)(r1g & (T_DIM - 1)) * HD;
            const float* sb1 = sinb + (size_t)(r1g & (T_DIM - 1)) * HD;
            __half* dst0 = Ch + (size_t)r0g * ldc + bn;
            __half* dst1 = Ch + (size_t)r1g * ldc + bn;
#pragma unroll
            for (int ni = 0; ni < 4; ni++) {
                const int d = dbase + ni * 4 + tq;
                const float c0 = cb0[d], s0 = sb0[d];
                const float c1 = cb1[d], s1 = sb1[d];
                float x1 = acc[mi][ni][0], x2 = acc[mi][ni][1];
                dst0[d]      = __float2half_rn((x1 * c0 - x2 * s0) * qscale);
                dst0[d + 64] = __float2half_rn((x2 * c0 + x1 * s0) * qscale);
                x1 = acc[mi][ni][2]; x2 = acc[mi][ni][3];
                dst1[d]      = __float2half_rn((x1 * c1 - x2 * s1) * qscale);
                dst1[d + 64] = __float2half_rn((x2 * c1 + x1 * s1) * qscale);
            }
        }
        return;
    }

#pragma unroll
    for (int mi = 0; mi < 4; mi++) {
#pragma unroll
        for (int ni = 0; ni < 4; ni++) {
            const int row = bm + wm + mi * 16 + g;
            const int col = bn + wn + ni * 8 + 2 * tq;
            if (mode == 1) {
                *(__half2*)&Ch[(size_t)row * ldc + col] =
                    __floats2half2_rn(acc[mi][ni][0], acc[mi][ni][1]);
                *(__half2*)&Ch[(size_t)(row + 8) * ldc + col] =
                    __floats2half2_rn(acc[mi][ni][2], acc[mi][ni][3]);
            } else {
                *(float2*)&Cf[(size_t)row * ldc + col] =
                    make_float2(acc[mi][ni][0], acc[mi][ni][1]);
                *(float2*)&Cf[(size_t)(row + 8) * ldc + col] =
                    make_float2(acc[mi][ni][2], acc[mi][ni][3]);
            }
        }
    }
}

#define ATT_SCALE 0.08838834764831845f   // 1/sqrt(128)

// Fused QKV: bx 0..15 -> Q (half+rope+scale), 16..19 -> K (half+rope), 20..23 -> V
__global__ __launch_bounds__(256, 2) void gemm_qkv_h(
    const __half* __restrict__ x,
    const __half* __restrict__ WqT, const __half* __restrict__ WkT,
    const __half* __restrict__ WvT,
    __half* __restrict__ qp, __half* __restrict__ kp, __half* __restrict__ vp,
    const float* __restrict__ cosb, const float* __restrict__ sinb)
{
    extern __shared__ __half smh[];
    const int bx = blockIdx.x;
    const __half* Bt; __half* Ch; int ldc; int bn; int mode; float qs;
    if (bx < 16)      { Bt = WqT; Ch = qp; ldc = QW; bn = bx * 128; mode = 2; qs = ATT_SCALE; }
    else if (bx < 20) { Bt = WkT; Ch = kp; ldc = KW; bn = (bx - 16) * 128; mode = 2; qs = 1.0f; }
    else              { Bt = WvT; Ch = vp; ldc = KW; bn = (bx - 20) * 128; mode = 1; qs = 1.0f; }
    gemm_h_core(x, Bt, nullptr, Ch, ldc, blockIdx.y * 128, bn, mode, qs, cosb, sinb, smh);
}

__global__ __launch_bounds__(256, 2) void gemm_wo_h(
    const __half* __restrict__ A, const __half* __restrict__ WoT,
    float* __restrict__ C)
{
    extern __shared__ __half smh[];
    gemm_h_core(A, WoT, C, nullptr, HID, blockIdx.y * 128, blockIdx.x * 128, 0, 1.0f,
                nullptr, nullptr, smh);
}

// ---------------------------------------------------------------------------
// fp16 flash attention, FA2-style register P reuse (no P smem, one sync/tile).
// BM=128 (8 warps x m16), BN=128, double-buffered K/V. Q pre-scaled upstream.
// ---------------------------------------------------------------------------
#define FBM 128
#define FBN 128
#define KVST 136                       // halves per K/V row
#define KV_STG (128 * KVST)            // halves per stage
#define FL_SMEM (4 * KV_STG * 2)       // 139264 B

__global__ __launch_bounds__(256, 1) void flash_h16(
    const __half* __restrict__ q, const __half* __restrict__ k,
    const __half* __restrict__ v, __half* __restrict__ o)
{
    extern __shared__ __half smh[];
    __half* Ks = smh;                  // [2][128][136]
    __half* Vs = Ks + 2 * KV_STG;      // [2][128][136]

    const int tid  = threadIdx.x;
    const int lane = tid & 31;
    const int warp = tid >> 5;
    const int g = lane >> 2;
    const int tq = lane & 3;
    const int wm = warp * 16;
    const int lr = lane & 15;
    const int lc = (lane >> 4) * 8;
    const int i0 = (gridDim.x - 1 - (int)blockIdx.x) * FBM;   // heavy CTAs first
    const int h  = blockIdx.y;
    const int b  = blockIdx.z;
    const int kh = h >> 2;

    const __half* qbase = q + ((size_t)b * T_DIM + i0) * QW + h * HD;
    const __half* kbase = k + ((size_t)b * T_DIM) * KW + kh * HD;
    const __half* vbase = v + ((size_t)b * T_DIM) * KW + kh * HD;

    // Q fragments: 8 k16-chunks covering d=128 (already scaled by 1/sqrt(d))
    uint32_t qf[8][4];
    {
        const __half* q0 = qbase + (size_t)(wm + g) * QW;
        const __half* q8 = q0 + (size_t)8 * QW;
#pragma unroll
        for (int kc = 0; kc < 8; kc++) {
            const int c = kc * 16 + 2 * tq;
            qf[kc][0] = *(const uint32_t*)(q0 + c);
            qf[kc][1] = *(const uint32_t*)(q8 + c);
            qf[kc][2] = *(const uint32_t*)(q0 + c + 8);
            qf[kc][3] = *(const uint32_t*)(q8 + c + 8);
        }
    }

    float O[16][4];
#pragma unroll
    for (int ni = 0; ni < 16; ni++)
#pragma unroll
        for (int r = 0; r < 4; r++) O[ni][r] = 0.0f;
    float m0 = -INFINITY, m1 = -INFINITY, l0 = 0.0f, l1 = 0.0f;

    const int row0 = i0 + wm + g;
    const int row1 = row0 + 8;

#define LOAD_KV(st, j0) { \
    __half* Kd = Ks + (st) * KV_STG; \
    __half* Vd = Vs + (st) * KV_STG; \
    _Pragma("unroll") \
    for (int j = 0; j < 8; j++) { \
        int i = tid + 256 * j; int row = i >> 4; int c = i & 15; \
        cp16(Kd + row * KVST + c * 8, kbase + (size_t)((j0) + row) * KW + c * 8); \
        cp16(Vd + row * KVST + c * 8, vbase + (size_t)((j0) + row) * KW + c * 8); \
    } \
    cp_commit(); }

    const int ntiles = i0 / FBN + 1;
    LOAD_KV(0, 0)

    for (int jt = 0; jt < ntiles; jt++) {
        const int j0 = jt * FBN;
        cp_wait<0>();
        __syncthreads();
        if (jt + 1 < ntiles) LOAD_KV((jt + 1) & 1, j0 + FBN)

        const __half* Kst = Ks + (jt & 1) * KV_STG;
        const __half* Vst = Vs + (jt & 1) * KV_STG;

        // S = Q @ K^T : 8 k16-chunks x 16 n8-tiles (K frags via ldmatrix)
        float S[16][4];
#pragma unroll
        for (int ni = 0; ni < 16; ni++)
#pragma unroll
            for (int r = 0; r < 4; r++) S[ni][r] = 0.0f;

#pragma unroll
        for (int kc = 0; kc < 8; kc++) {
#pragma unroll
            for (int nj = 0; nj < 8; nj++) {
                uint32_t r0, r1, r2, r3;
                ldmx4(r0, r1, r2, r3,
                      Kst + (nj * 16 + lr) * KVST + kc * 16 + lc);
                uint32_t b0[2] = {r0, r2}, b1[2] = {r1, r3};
                mma_f16(S[2 * nj],     qf[kc], b0);
                mma_f16(S[2 * nj + 1], qf[kc], b1);
            }
        }

        if (j0 == i0) {   // diagonal tile: causal mask
#pragma unroll
            for (int ni = 0; ni < 16; ni++) {
                const int col = j0 + ni * 8 + 2 * tq;
                if (col     > row0) S[ni][0] = -1e30f;
                if (col + 1 > row0) S[ni][1] = -1e30f;
                if (col     > row1) S[ni][2] = -1e30f;
                if (col + 1 > row1) S[ni][3] = -1e30f;
            }
        }

        // online softmax
        float rm0 = -INFINITY, rm1 = -INFINITY;
#pragma unroll
        for (int ni = 0; ni < 16; ni++) {
            rm0 = fmaxf(rm0, fmaxf(S[ni][0], S[ni][1]));
            rm1 = fmaxf(rm1, fmaxf(S[ni][2], S[ni][3]));
        }
        rm0 = fmaxf(rm0, __shfl_xor_sync(0xffffffffu, rm0, 1));
        rm0 = fmaxf(rm0, __shfl_xor_sync(0xffffffffu, rm0, 2));
        rm1 = fmaxf(rm1, __shfl_xor_sync(0xffffffffu, rm1, 1));
        rm1 = fmaxf(rm1, __shfl_xor_sync(0xffffffffu, rm1, 2));

        const float mn0 = fmaxf(m0, rm0);
        const float mn1 = fmaxf(m1, rm1);
        const float a0 = __expf(m0 - mn0);
        const float a1 = __expf(m1 - mn1);
        m0 = mn0; m1 = mn1;

        float rs0 = 0.0f, rs1 = 0.0f;
#pragma unroll
        for (int ni = 0; ni < 16; ni++) {
            S[ni][0] = __expf(S[ni][0] - mn0);
            S[ni][1] = __expf(S[ni][1] - mn0);
            S[ni][2] = __expf(S[ni][2] - mn1);
            S[ni][3] = __expf(S[ni][3] - mn1);
            rs0 += S[ni][0] + S[ni][1];
            rs1 += S[ni][2] + S[ni][3];
        }
        rs0 += __shfl_xor_sync(0xffffffffu, rs0, 1);
        rs0 += __shfl_xor_sync(0xffffffffu, rs0, 2);
        rs1 += __shfl_xor_sync(0xffffffffu, rs1, 1);
        rs1 += __shfl_xor_sync(0xffffffffu, rs1, 2);
        l0 = l0 * a0 + rs0;
        l1 = l1 * a1 + rs1;

#pragma unroll
        for (int ni = 0; ni < 16; ni++) {
            O[ni][0] *= a0; O[ni][1] *= a0;
            O[ni][2] *= a1; O[ni][3] *= a1;
        }

        // O += P @ V : P comes straight from S registers (FA2 layout identity)
        const int lrow = (lane & 7) + 8 * ((lane >> 3) & 1);
        const int lcol = 8 * (lane >> 4);
#pragma unroll
        for (int kc = 0; kc < 8; kc++) {
            uint32_t pa[4];
            pa[0] = pack2(S[2 * kc][0],     S[2 * kc][1]);
            pa[1] = pack2(S[2 * kc][2],     S[2 * kc][3]);
            pa[2] = pack2(S[2 * kc + 1][0], S[2 * kc + 1][1]);
            pa[3] = pack2(S[2 * kc + 1][2], S[2 * kc + 1][3]);
            const __half* vrow = Vst + (kc * 16 + lrow) * KVST + lcol;
#pragma unroll
            for (int ni2 = 0; ni2 < 8; ni2++) {
                uint32_t r0, r1, r2, r3;
                ldmx4_trans(r0, r1, r2, r3, vrow + ni2 * 16);
                uint32_t b0[2] = {r0, r1}, b1[2] = {r2, r3};
                mma_f16(O[2 * ni2],     pa, b0);
                mma_f16(O[2 * ni2 + 1], pa, b1);
            }
        }
    }
#undef LOAD_KV

    // epilogue: normalize, write half attn
    const float il0 = 1.0f / l0;
    const float il1 = 1.0f / l1;
    __half* ob = o + ((size_t)b * T_DIM + i0) * QW + h * HD;
#pragma unroll
    for (int ni = 0; ni < 16; ni++) {
        *(__half2*)(ob + (size_t)(wm + g) * QW + ni * 8 + 2 * tq) =
            __floats2half2_rn(O[ni][0] * il0, O[ni][1] * il0);
        *(__half2*)(ob + (size_t)(wm + g + 8) * QW + ni * 8 + 2 * tq) =
            __floats2half2_rn(O[ni][2] * il1, O[ni][3] * il1);
    }
}

// ---------------------------------------------------------------------------
extern "C" void kernel_launch(void* const* d_in, const int* in_sizes, int n_in,
                              void* d_out, int out_size)
{
    const float* x    = (const float*)d_in[0];
    const float* cosb = (const float*)d_in[1];
    const float* sinb = (const float*)d_in[2];
    const float* Wq   = (const float*)d_in[3];
    const float* Wk   = (const float*)d_in[4];
    const float* Wv   = (const float*)d_in[5];
    const float* Wo   = (const float*)d_in[6];
    float* out = (float*)d_out;

    __half *xh, *qh, *khh, *vh, *ah, *wqh, *wkh, *wvh, *woh;
    cudaGetSymbolAddress((void**)&xh, g_xh);
    cudaGetSymbolAddress((void**)&qh, g_qh);
    cudaGetSymbolAddress((void**)&khh, g_kh);
    cudaGetSymbolAddress((void**)&vh, g_vh);
    cudaGetSymbolAddress((void**)&ah, g_ah);
    cudaGetSymbolAddress((void**)&wqh, g_wqh);
    cudaGetSymbolAddress((void**)&wkh, g_wkh);
    cudaGetSymbolAddress((void**)&wvh, g_wvh);
    cudaGetSymbolAddress((void**)&woh, g_woh);

    cudaFuncSetAttribute(gemm_qkv_h, cudaFuncAttributeMaxDynamicSharedMemorySize, GH_SMEM);
    cudaFuncSetAttribute(gemm_wo_h, cudaFuncAttributeMaxDynamicSharedMemorySize, GH_SMEM);
    cudaFuncSetAttribute(flash_h16, cudaFuncAttributeMaxDynamicSharedMemorySize, FL_SMEM);

    // Fused pre-pass: x->half and 4 weight transposes in one launch
    prepass_kernel<<<PP_TOTAL, 256>>>(x, Wq, Wk, Wv, Wo, xh, wqh, wkh, wvh, woh);

    // QKV projections with fused in-register RoPE (Q scaled) / direct half (V)
    gemm_qkv_h<<<dim3(24, ROWS / 128), 256, GH_SMEM>>>(
        xh, wqh, wkh, wvh, qh, khh, vh, cosb, sinb);

    // Attention (fp16, FA2 register reuse)
    flash_h16<<<dim3(T_DIM / FBM, NH, B_DIM), 256, FL_SMEM>>>(qh, khh, vh, ah);

    // Output projection (fp16)
    gemm_wo_h<<<dim3(HID / 128, ROWS / 128), 256, GH_SMEM>>>(ah, woh, out);
}